// round 16
// baseline (speedup 1.0000x reference)
#include <cuda_runtime.h>
#include <cuda_fp16.h>
#include <cstdint>

typedef uint32_t u32;

#define SQRTD_F 11.313708498984761f
#define RSB 272            // row stride bytes (17 x 16B chunks)

// smem byte offsets
#define SM_PIH  0          // Pi hi : 128*272 = 34816
#define SM_PIL  34816      // Pi lo
#define SM_AH   69632      // A hi : 64*272 = 17408
#define SM_AL   87040      // A lo
#define SM_MISC 104448
#define SMEM_BYTES 107520

// precomputed packed Pi (hi tile then lo tile, smem-identical layout) + tables
__device__ uint4  g_pip[4352];
__device__ u32    g_csd2[256];    // (csd[lo nibble], csd[hi nibble]) fp16 pair
__device__ float  g_mid[15];

static __device__ __forceinline__ u32 smem_u32(const void* p) {
    u32 r;
    asm("{ .reg .u64 t; cvta.to.shared.u64 t, %1; cvt.u32.u64 %0, t; }" : "=r"(r) : "l"(p));
    return r;
}
static __device__ __forceinline__ u32 hpack(__half a, __half b) {
    return (u32)__half_as_ushort(a) | ((u32)__half_as_ushort(b) << 16);
}
static __device__ __forceinline__ int csw(int c) { return c ^ ((c & 8) >> 1); }

static __device__ __forceinline__ void mma16(float c[4], u32 a0, u32 a1, u32 a2, u32 a3,
                                             u32 b0, u32 b1) {
    asm volatile(
        "mma.sync.aligned.m16n8k16.row.col.f32.f16.f16.f32 "
        "{%0,%1,%2,%3},{%4,%5,%6,%7},{%8,%9},{%0,%1,%2,%3};"
        : "+f"(c[0]), "+f"(c[1]), "+f"(c[2]), "+f"(c[3])
        : "r"(a0), "r"(a1), "r"(a2), "r"(a3), "r"(b0), "r"(b1));
}
#define LDSM_X4(r, a) \
    asm volatile("ldmatrix.sync.aligned.m8n8.x4.shared.b16 {%0,%1,%2,%3}, [%4];" \
        : "=r"((r)[0]), "=r"((r)[1]), "=r"((r)[2]), "=r"((r)[3]) : "r"(a))
#define LDSM_X4T(r, a) \
    asm volatile("ldmatrix.sync.aligned.m8n8.x4.trans.shared.b16 {%0,%1,%2,%3}, [%4];" \
        : "=r"((r)[0]), "=r"((r)[1]), "=r"((r)[2]), "=r"((r)[3]) : "r"(a))
#define CP16(s, g) \
    asm volatile("cp.async.cg.shared.global [%0], [%1], 16;" :: "r"(s), "l"(g))

// exact binary-search quantizer: idx = #{l : y > mid[l]} for sorted mids
static __device__ __forceinline__ int quant_idx(float y, const float* m) {
    bool b3 = y > m[7];
    float mA = b3 ? m[11] : m[3];
    bool b2 = y > mA;
    float mB = b3 ? (b2 ? m[13] : m[9]) : (b2 ? m[5] : m[1]);
    bool b1 = y > mB;
    float mC = b3 ? (b2 ? (b1 ? m[14] : m[12]) : (b1 ? m[10] : m[8]))
                  : (b2 ? (b1 ? m[6]  : m[4])  : (b1 ? m[2]  : m[0]));
    bool b0 = y > mC;
    return (((int)b3) << 3) | (((int)b2) << 2) | (((int)b1) << 1) | (int)b0;
}

// pack 8 floats into hi/lo uint4
static __device__ __forceinline__ void pack8(const float4 a, const float4 b,
                                             uint4& hi, uint4& lo) {
    __half h0 = __float2half_rn(a.x), h1 = __float2half_rn(a.y);
    __half h2 = __float2half_rn(a.z), h3 = __float2half_rn(a.w);
    __half h4 = __float2half_rn(b.x), h5 = __float2half_rn(b.y);
    __half h6 = __float2half_rn(b.z), h7 = __float2half_rn(b.w);
    hi.x = hpack(h0, h1); hi.y = hpack(h2, h3);
    hi.z = hpack(h4, h5); hi.w = hpack(h6, h7);
    lo.x = hpack(__float2half_rn(a.x - __half2float(h0)),
                 __float2half_rn(a.y - __half2float(h1)));
    lo.y = hpack(__float2half_rn(a.z - __half2float(h2)),
                 __float2half_rn(a.w - __half2float(h3)));
    lo.z = hpack(__float2half_rn(b.x - __half2float(h4)),
                 __float2half_rn(b.y - __half2float(h5)));
    lo.w = hpack(__float2half_rn(b.z - __half2float(h6)),
                 __float2half_rn(b.w - __half2float(h7)));
}

// ---------------- setup kernel: pack Pi + tables once per launch ----------------
__global__ __launch_bounds__(256)
void tq_setup(const float* __restrict__ Pi, const float* __restrict__ cbk) {
    const int tid = threadIdx.x;
    const int r = blockIdx.x * 16 + (tid >> 4);
    const int c = tid & 15;
    const float4* pp = (const float4*)(Pi + r * 128 + c * 8);
    uint4 hi, lo;
    pack8(pp[0], pp[1], hi, lo);
    g_pip[r * 17 + csw(c)] = hi;
    g_pip[2176 + r * 17 + csw(c)] = lo;
    if (c == 0) {
        uint4 z = make_uint4(0, 0, 0, 0);
        g_pip[r * 17 + 16] = z;
        g_pip[2176 + r * 17 + 16] = z;
    }
    if (blockIdx.x == 0) {
        int i0 = tid & 15, i1 = tid >> 4;
        __half c0 = __float2half_rn(__fdiv_rn(cbk[i0], SQRTD_F));
        __half c1 = __float2half_rn(__fdiv_rn(cbk[i1], SQRTD_F));
        g_csd2[tid] = hpack(c0, c1);
        if (tid < 15) g_mid[tid] = (cbk[tid] + cbk[tid + 1]) * 0.5f;
    }
}

// ---------------- main kernel: 2 token-tiles (128 tokens) per CTA ----------------
__global__ __launch_bounds__(256, 2)
void tq_fused(const float* __restrict__ x, float* __restrict__ out) {
    extern __shared__ char sm[];
    u32*    s_csd2  = (u32*)(sm + SM_MISC);             // 256 u32
    float*  s_mid   = (float*)(sm + SM_MISC + 1024);    // 15 f32
    float*  s_part  = (float*)(sm + SM_MISC + 1152);    // 256 f32
    float*  s_scale = (float*)(sm + SM_MISC + 2176);    // 64 f32
    float*  s_nh    = (float*)(sm + SM_MISC + 2432);    // 64 f32

    const int tid = threadIdx.x;
    const int wid = tid >> 5, lane = tid & 31;
    const int g = lane >> 2, t = lane & 3;
    const int mrow0 = (wid >> 2) * 32;
    const int ncol0 = (wid & 3) * 32;
    const int tokbase = blockIdx.x << 7;    // 128 tokens per CTA

    const u32 sb = smem_u32(sm);
    const int xr_row = tid >> 2, xr_q = tid & 3;

    // ---- copy packed Pi tiles (hi+lo) via cp.async (ONCE per 128 tokens) ----
    {
        const uint4* gp = g_pip;
        #pragma unroll
        for (int i = 0; i < 17; i++) {
            const int idx = tid + i * 256;
            CP16(sb + SM_PIH + idx * 16, gp + idx);
        }
        asm volatile("cp.async.commit_group;" ::: "memory");
    }

    // ---- prologue: load tile-0 x into registers ----
    float4 xv[8];
    {
        const float4* xr = (const float4*)(x + (size_t)(tokbase + xr_row) * 128 + xr_q * 32);
        #pragma unroll
        for (int e = 0; e < 8; e++) xv[e] = xr[e];
    }
    s_csd2[tid] = g_csd2[tid];
    if (tid < 15) s_mid[tid] = g_mid[tid];
    asm volatile("cp.async.wait_group 0;" ::: "memory");

    // per-thread LDSM lane geometry (tile-independent)
    const int lrow = (lane & 7) + ((lane >> 3) & 1) * 8;
    const int lq = lane >> 4;
    const u32 aAh0 = sb + SM_AH + (u32)(mrow0 + lrow) * RSB;
    const u32 aAh1 = aAh0 + 16 * RSB;
    const u32 aAl0 = aAh0 + (SM_AL - SM_AH);
    const u32 aAl1 = aAh1 + (SM_AL - SM_AH);
    const u32 aBh0 = sb + SM_PIH + (u32)(ncol0 + lrow) * RSB;
    const u32 aBh1 = aBh0 + 16 * RSB;
    const u32 aBl0 = aBh0 + (SM_PIL - SM_PIH);
    const u32 aBl1 = aBh1 + (SM_PIL - SM_PIH);

    #pragma unroll 1
    for (int tile = 0; tile < 2; tile++) {
        const int tok0 = tokbase + (tile << 6);

        if (tile == 1) __syncthreads();   // bwd done reading A before restage

        // ---- stage A hi/lo from registers; partial sum of squares ----
        {
            float ss = 0.f;
            #pragma unroll
            for (int e2 = 0; e2 < 4; e2++) {
                float4 a = xv[2 * e2], b = xv[2 * e2 + 1];
                ss += a.x * a.x + a.y * a.y + a.z * a.z + a.w * a.w;
                ss += b.x * b.x + b.y * b.y + b.z * b.z + b.w * b.w;
                uint4 hi, lo;
                pack8(a, b, hi, lo);
                char* p = sm + SM_AH + xr_row * RSB + csw(4 * xr_q + e2) * 16;
                *(uint4*)p = hi;
                *(uint4*)(p + (SM_AL - SM_AH)) = lo;
            }
            s_part[tid] = ss;
        }
        __syncthreads();

        // ---- norms (warps 0-1; other warps proceed into fwd chain) ----
        if (tid < 64) {
            float s = s_part[4 * tid] + s_part[4 * tid + 1]
                    + s_part[4 * tid + 2] + s_part[4 * tid + 3];
            float n = __fsqrt_rn(s);
            float cn = fmaxf(n, 1e-8f);
            s_scale[tid] = __fdiv_rn(SQRTD_F, cn);
            s_nh[tid] = __half2float(__float2half_rn(n));
        }

        float acc[2][4][4];
        #pragma unroll
        for (int i = 0; i < 2; i++)
            #pragma unroll
            for (int j = 0; j < 4; j++)
                #pragma unroll
                for (int k = 0; k < 4; k++) acc[i][j][k] = 0.f;

        // ---- forward: y_raw = x @ Pi^T (3-product hi/lo fp16) ----
        #pragma unroll
        for (int ks = 0; ks < 8; ks++) {
            const u32 co = (u32)(((2 * ks) ^ (ks & 4)) + lq) * 16;
            u32 bh0[4], bh1[4], bl0[4], bl1[4], ah0[4], ah1[4], al0[4], al1[4];
            LDSM_X4(bh0, aBh0 + co);
            LDSM_X4(bh1, aBh1 + co);
            LDSM_X4(bl0, aBl0 + co);
            LDSM_X4(bl1, aBl1 + co);
            LDSM_X4(ah0, aAh0 + co);
            LDSM_X4(ah1, aAh1 + co);
            LDSM_X4(al0, aAl0 + co);
            LDSM_X4(al1, aAl1 + co);
            u32 bh[4][2] = {{bh0[0],bh0[2]},{bh0[1],bh0[3]},{bh1[0],bh1[2]},{bh1[1],bh1[3]}};
            u32 bl[4][2] = {{bl0[0],bl0[2]},{bl0[1],bl0[3]},{bl1[0],bl1[2]},{bl1[1],bl1[3]}};
            #pragma unroll
            for (int nt = 0; nt < 4; nt++) {
                mma16(acc[0][nt], ah0[0], ah0[1], ah0[2], ah0[3], bh[nt][0], bh[nt][1]);
                mma16(acc[1][nt], ah1[0], ah1[1], ah1[2], ah1[3], bh[nt][0], bh[nt][1]);
            }
            #pragma unroll
            for (int nt = 0; nt < 4; nt++) {
                mma16(acc[0][nt], ah0[0], ah0[1], ah0[2], ah0[3], bl[nt][0], bl[nt][1]);
                mma16(acc[1][nt], ah1[0], ah1[1], ah1[2], ah1[3], bl[nt][0], bl[nt][1]);
            }
            #pragma unroll
            for (int nt = 0; nt < 4; nt++) {
                mma16(acc[0][nt], al0[0], al0[1], al0[2], al0[3], bh[nt][0], bh[nt][1]);
                mma16(acc[1][nt], al1[0], al1[1], al1[2], al1[3], bh[nt][0], bh[nt][1]);
            }
        }
        __syncthreads();

        // ---- prefetch next tile's x (latency hides under quantize + bwd) ----
        if (tile == 0) {
            const float4* xr = (const float4*)(x + (size_t)(tokbase + 64 + xr_row) * 128 + xr_q * 32);
            #pragma unroll
            for (int e = 0; e < 8; e++) xv[e] = xr[e];
        }

        // ---- quantize: y = y_raw*(sqrt_d/norm); paired-table lookup; write u32 ----
        {
            float mids[15];
            #pragma unroll
            for (int l = 0; l < 15; l++) mids[l] = s_mid[l];
            u32* aW = (u32*)(sm + SM_AH);
            #pragma unroll
            for (int mt = 0; mt < 2; mt++) {
                const int row0 = mrow0 + mt * 16 + g;
                const float sc0 = s_scale[row0];
                const float sc1 = s_scale[row0 + 8];
                #pragma unroll
                for (int nt = 0; nt < 4; nt++) {
                    const int p = (ncol0 >> 1) + nt * 4 + t;
                    const int woff = csw(p >> 2) * 4 + (p & 3);
                    {
                        int i0 = quant_idx(acc[mt][nt][0] * sc0, mids);
                        int i1 = quant_idx(acc[mt][nt][1] * sc0, mids);
                        aW[row0 * 68 + woff] = s_csd2[i0 | (i1 << 4)];
                    }
                    {
                        int i0 = quant_idx(acc[mt][nt][2] * sc1, mids);
                        int i1 = quant_idx(acc[mt][nt][3] * sc1, mids);
                        aW[(row0 + 8) * 68 + woff] = s_csd2[i0 | (i1 << 4)];
                    }
                    acc[mt][nt][0] = 0.f; acc[mt][nt][1] = 0.f;
                    acc[mt][nt][2] = 0.f; acc[mt][nt][3] = 0.f;
                }
            }
        }
        __syncthreads();

        // ---- backward: z = a_hat @ Pi (a_hi * Pi_hi via ldmatrix.trans) ----
        {
            const int cnq = (ncol0 >> 3) + lq;
            const u32 cb0 = (u32)csw(cnq) * 16;
            const u32 cb1 = (u32)csw(cnq + 2) * 16;
            const u32 tbase = sb + SM_PIH + (u32)lrow * RSB;
            #pragma unroll
            for (int ks = 0; ks < 8; ks++) {
                const u32 rb = tbase + (u32)(16 * ks) * RSB;
                const u32 co = (u32)(((2 * ks) ^ (ks & 4)) + lq) * 16;
                u32 th0[4], th1[4], ah0[4], ah1[4];
                LDSM_X4T(th0, rb + cb0);
                LDSM_X4T(th1, rb + cb1);
                LDSM_X4(ah0, aAh0 + co);
                LDSM_X4(ah1, aAh1 + co);
                u32 bh[4][2] = {{th0[0],th0[1]},{th0[2],th0[3]},{th1[0],th1[1]},{th1[2],th1[3]}};
                #pragma unroll
                for (int nt = 0; nt < 4; nt++) {
                    mma16(acc[0][nt], ah0[0], ah0[1], ah0[2], ah0[3], bh[nt][0], bh[nt][1]);
                    mma16(acc[1][nt], ah1[0], ah1[1], ah1[2], ah1[3], bh[nt][0], bh[nt][1]);
                }
            }
        }

        // ---- epilogue: scale by fp16-roundtripped norm, store float2 ----
        #pragma unroll
        for (int mt = 0; mt < 2; mt++) {
            #pragma unroll
            for (int nt = 0; nt < 4; nt++) {
                int row0 = mrow0 + mt * 16 + g;
                int col  = ncol0 + nt * 8 + 2 * t;
                float nh0 = s_nh[row0];
                float nh1 = s_nh[row0 + 8];
                *(float2*)(out + (size_t)(tok0 + row0) * 128 + col) =
                    make_float2(acc[mt][nt][0] * nh0, acc[mt][nt][1] * nh0);
                *(float2*)(out + (size_t)(tok0 + row0 + 8) * 128 + col) =
                    make_float2(acc[mt][nt][2] * nh1, acc[mt][nt][3] * nh1);
            }
        }
    }
}

extern "C" void kernel_launch(void* const* d_in, const int* in_sizes, int n_in,
                              void* d_out, int out_size) {
    const float* x   = (const float*)d_in[0];
    const float* Pi  = (const float*)d_in[1];
    const float* cbk = (const float*)d_in[2];
    float* out = (float*)d_out;

    int ntok = in_sizes[0] / 128;
    int blocks = ntok / 128;

    cudaFuncSetAttribute(tq_fused, cudaFuncAttributeMaxDynamicSharedMemorySize, SMEM_BYTES);
    tq_setup<<<8, 256>>>(Pi, cbk);
    tq_fused<<<blocks, 256, SMEM_BYTES>>>(x, out);
}

// round 17
// speedup vs baseline: 1.0708x; 1.0708x over previous
#include <cuda_runtime.h>
#include <cuda_fp16.h>
#include <cstdint>

typedef uint32_t u32;

#define SQRTD_F 11.313708498984761f
#define RSB 272            // row stride bytes (17 x 16B chunks)

// smem byte offsets
#define SM_PIH  0          // Pi hi : 128*272 = 34816
#define SM_PIL  34816      // Pi lo
#define SM_AH   69632      // A hi : 64 x 272 = 17408
#define SM_AL   87040      // A lo
#define SM_MISC 104448
#define SMEM_BYTES 107520

// precomputed packed Pi (hi tile then lo tile, smem-identical layout) + tables
__device__ uint4  g_pip[4352];
__device__ u32    g_csd2[256];    // (csd[lo nibble], csd[hi nibble]) fp16 pair
__device__ float  g_mid[15];

static __device__ __forceinline__ u32 smem_u32(const void* p) {
    u32 r;
    asm("{ .reg .u64 t; cvta.to.shared.u64 t, %1; cvt.u32.u64 %0, t; }" : "=r"(r) : "l"(p));
    return r;
}
static __device__ __forceinline__ u32 hpack(__half a, __half b) {
    return (u32)__half_as_ushort(a) | ((u32)__half_as_ushort(b) << 16);
}
static __device__ __forceinline__ int csw(int c) { return c ^ ((c & 8) >> 1); }

static __device__ __forceinline__ void mma16(float c[4], u32 a0, u32 a1, u32 a2, u32 a3,
                                             u32 b0, u32 b1) {
    asm volatile(
        "mma.sync.aligned.m16n8k16.row.col.f32.f16.f16.f32 "
        "{%0,%1,%2,%3},{%4,%5,%6,%7},{%8,%9},{%0,%1,%2,%3};"
        : "+f"(c[0]), "+f"(c[1]), "+f"(c[2]), "+f"(c[3])
        : "r"(a0), "r"(a1), "r"(a2), "r"(a3), "r"(b0), "r"(b1));
}
#define LDSM_X4(r, a) \
    asm volatile("ldmatrix.sync.aligned.m8n8.x4.shared.b16 {%0,%1,%2,%3}, [%4];" \
        : "=r"((r)[0]), "=r"((r)[1]), "=r"((r)[2]), "=r"((r)[3]) : "r"(a))
#define LDSM_X4T(r, a) \
    asm volatile("ldmatrix.sync.aligned.m8n8.x4.trans.shared.b16 {%0,%1,%2,%3}, [%4];" \
        : "=r"((r)[0]), "=r"((r)[1]), "=r"((r)[2]), "=r"((r)[3]) : "r"(a))
#define CP16(s, g) \
    asm volatile("cp.async.cg.shared.global [%0], [%1], 16;" :: "r"(s), "l"(g))

// exact binary-search quantizer: idx = #{l : y > mid[l]} for sorted mids
static __device__ __forceinline__ int quant_idx(float y, const float* m) {
    bool b3 = y > m[7];
    float mA = b3 ? m[11] : m[3];
    bool b2 = y > mA;
    float mB = b3 ? (b2 ? m[13] : m[9]) : (b2 ? m[5] : m[1]);
    bool b1 = y > mB;
    float mC = b3 ? (b2 ? (b1 ? m[14] : m[12]) : (b1 ? m[10] : m[8]))
                  : (b2 ? (b1 ? m[6]  : m[4])  : (b1 ? m[2]  : m[0]));
    bool b0 = y > mC;
    return (((int)b3) << 3) | (((int)b2) << 2) | (((int)b1) << 1) | (int)b0;
}

// pack 8 floats into hi/lo uint4
static __device__ __forceinline__ void pack8(const float4 a, const float4 b,
                                             uint4& hi, uint4& lo) {
    __half h0 = __float2half_rn(a.x), h1 = __float2half_rn(a.y);
    __half h2 = __float2half_rn(a.z), h3 = __float2half_rn(a.w);
    __half h4 = __float2half_rn(b.x), h5 = __float2half_rn(b.y);
    __half h6 = __float2half_rn(b.z), h7 = __float2half_rn(b.w);
    hi.x = hpack(h0, h1); hi.y = hpack(h2, h3);
    hi.z = hpack(h4, h5); hi.w = hpack(h6, h7);
    lo.x = hpack(__float2half_rn(a.x - __half2float(h0)),
                 __float2half_rn(a.y - __half2float(h1)));
    lo.y = hpack(__float2half_rn(a.z - __half2float(h2)),
                 __float2half_rn(a.w - __half2float(h3)));
    lo.z = hpack(__float2half_rn(b.x - __half2float(h4)),
                 __float2half_rn(b.y - __half2float(h5)));
    lo.w = hpack(__float2half_rn(b.z - __half2float(h6)),
                 __float2half_rn(b.w - __half2float(h7)));
}

// ---------------- setup kernel: pack Pi + tables once per launch ----------------
__global__ __launch_bounds__(256)
void tq_setup(const float* __restrict__ Pi, const float* __restrict__ cbk) {
    const int tid = threadIdx.x;
    const int r = blockIdx.x * 16 + (tid >> 4);
    const int c = tid & 15;
    const float4* pp = (const float4*)(Pi + r * 128 + c * 8);
    uint4 hi, lo;
    pack8(pp[0], pp[1], hi, lo);
    g_pip[r * 17 + csw(c)] = hi;
    g_pip[2176 + r * 17 + csw(c)] = lo;
    if (c == 0) {
        uint4 z = make_uint4(0, 0, 0, 0);
        g_pip[r * 17 + 16] = z;
        g_pip[2176 + r * 17 + 16] = z;
    }
    if (blockIdx.x == 0) {
        int i0 = tid & 15, i1 = tid >> 4;
        __half c0 = __float2half_rn(__fdiv_rn(cbk[i0], SQRTD_F));
        __half c1 = __float2half_rn(__fdiv_rn(cbk[i1], SQRTD_F));
        g_csd2[tid] = hpack(c0, c1);
        if (tid < 15) g_mid[tid] = (cbk[tid] + cbk[tid + 1]) * 0.5f;
    }
}

// ---------------- main kernel: persistent CTAs, loop over 64-token tiles ----------------
__global__ __launch_bounds__(256, 2)
void tq_fused(const float* __restrict__ x, float* __restrict__ out, int ntiles) {
    extern __shared__ char sm[];
    u32*    s_csd2  = (u32*)(sm + SM_MISC);             // 256 u32
    float*  s_mid   = (float*)(sm + SM_MISC + 1024);    // 15 f32
    float*  s_part  = (float*)(sm + SM_MISC + 1152);    // 256 f32
    float*  s_scale = (float*)(sm + SM_MISC + 2176);    // 64 f32
    float*  s_nh    = (float*)(sm + SM_MISC + 2432);    // 64 f32

    const int tid = threadIdx.x;
    const int wid = tid >> 5, lane = tid & 31;
    const int g = lane >> 2, t = lane & 3;
    const int mrow0 = (wid >> 2) * 32;
    const int ncol0 = (wid & 3) * 32;

    const u32 sb = smem_u32(sm);
    const int xr_row = tid >> 2, xr_q = tid & 3;

    // ---- stage packed Pi tiles via cp.async (ONCE per persistent CTA) ----
    {
        const uint4* gp = g_pip;
        #pragma unroll
        for (int i = 0; i < 17; i++) {
            const int idx = tid + i * 256;
            CP16(sb + SM_PIH + idx * 16, gp + idx);
        }
        asm volatile("cp.async.commit_group;" ::: "memory");
    }

    // ---- prologue: load first tile's x into registers ----
    int tile = blockIdx.x;
    float4 xv[8];
    {
        const float4* xr = (const float4*)(x + ((size_t)tile * 64 + xr_row) * 128 + xr_q * 32);
        #pragma unroll
        for (int e = 0; e < 8; e++) xv[e] = xr[e];
    }
    s_csd2[tid] = g_csd2[tid];
    if (tid < 15) s_mid[tid] = g_mid[tid];
    asm volatile("cp.async.wait_group 0;" ::: "memory");

    // per-thread LDSM lane geometry (tile-independent)
    const int lrow = (lane & 7) + ((lane >> 3) & 1) * 8;
    const int lq = lane >> 4;
    const u32 aAh0 = sb + SM_AH + (u32)(mrow0 + lrow) * RSB;
    const u32 aAh1 = aAh0 + 16 * RSB;
    const u32 aAl0 = aAh0 + (SM_AL - SM_AH);
    const u32 aAl1 = aAh1 + (SM_AL - SM_AH);
    const u32 aBh0 = sb + SM_PIH + (u32)(ncol0 + lrow) * RSB;
    const u32 aBh1 = aBh0 + 16 * RSB;
    const u32 aBl0 = aBh0 + (SM_PIL - SM_PIH);
    const u32 aBl1 = aBh1 + (SM_PIL - SM_PIH);

    bool first = true;
    #pragma unroll 1
    for (; tile < ntiles; tile += gridDim.x) {
        const size_t tok0 = (size_t)tile * 64;
        const int ntile = tile + gridDim.x;

        if (!first) __syncthreads();   // previous bwd done reading A before restage
        first = false;

        // ---- stage A hi/lo from registers; partial sum of squares ----
        {
            float ss = 0.f;
            #pragma unroll
            for (int e2 = 0; e2 < 4; e2++) {
                float4 a = xv[2 * e2], b = xv[2 * e2 + 1];
                ss += a.x * a.x + a.y * a.y + a.z * a.z + a.w * a.w;
                ss += b.x * b.x + b.y * b.y + b.z * b.z + b.w * b.w;
                uint4 hi, lo;
                pack8(a, b, hi, lo);
                char* p = sm + SM_AH + xr_row * RSB + csw(4 * xr_q + e2) * 16;
                *(uint4*)p = hi;
                *(uint4*)(p + (SM_AL - SM_AH)) = lo;
            }
            s_part[tid] = ss;
        }
        __syncthreads();

        // ---- norms (warps 0-1; other warps proceed into fwd chain) ----
        if (tid < 64) {
            float s = s_part[4 * tid] + s_part[4 * tid + 1]
                    + s_part[4 * tid + 2] + s_part[4 * tid + 3];
            float n = __fsqrt_rn(s);
            float cn = fmaxf(n, 1e-8f);
            s_scale[tid] = __fdiv_rn(SQRTD_F, cn);
            s_nh[tid] = __half2float(__float2half_rn(n));
        }

        float acc[2][4][4];
        #pragma unroll
        for (int i = 0; i < 2; i++)
            #pragma unroll
            for (int j = 0; j < 4; j++)
                #pragma unroll
                for (int k = 0; k < 4; k++) acc[i][j][k] = 0.f;

        // ---- forward: y_raw = x @ Pi^T (3-product hi/lo fp16) ----
        #pragma unroll
        for (int ks = 0; ks < 8; ks++) {
            const u32 co = (u32)(((2 * ks) ^ (ks & 4)) + lq) * 16;
            u32 bh0[4], bh1[4], bl0[4], bl1[4], ah0[4], ah1[4], al0[4], al1[4];
            LDSM_X4(bh0, aBh0 + co);
            LDSM_X4(bh1, aBh1 + co);
            LDSM_X4(bl0, aBl0 + co);
            LDSM_X4(bl1, aBl1 + co);
            LDSM_X4(ah0, aAh0 + co);
            LDSM_X4(ah1, aAh1 + co);
            LDSM_X4(al0, aAl0 + co);
            LDSM_X4(al1, aAl1 + co);
            u32 bh[4][2] = {{bh0[0],bh0[2]},{bh0[1],bh0[3]},{bh1[0],bh1[2]},{bh1[1],bh1[3]}};
            u32 bl[4][2] = {{bl0[0],bl0[2]},{bl0[1],bl0[3]},{bl1[0],bl1[2]},{bl1[1],bl1[3]}};
            #pragma unroll
            for (int nt = 0; nt < 4; nt++) {
                mma16(acc[0][nt], ah0[0], ah0[1], ah0[2], ah0[3], bh[nt][0], bh[nt][1]);
                mma16(acc[1][nt], ah1[0], ah1[1], ah1[2], ah1[3], bh[nt][0], bh[nt][1]);
            }
            #pragma unroll
            for (int nt = 0; nt < 4; nt++) {
                mma16(acc[0][nt], ah0[0], ah0[1], ah0[2], ah0[3], bl[nt][0], bl[nt][1]);
                mma16(acc[1][nt], ah1[0], ah1[1], ah1[2], ah1[3], bl[nt][0], bl[nt][1]);
            }
            #pragma unroll
            for (int nt = 0; nt < 4; nt++) {
                mma16(acc[0][nt], al0[0], al0[1], al0[2], al0[3], bh[nt][0], bh[nt][1]);
                mma16(acc[1][nt], al1[0], al1[1], al1[2], al1[3], bh[nt][0], bh[nt][1]);
            }
        }
        __syncthreads();

        // ---- prefetch next tile's x (latency hides under quantize + bwd) ----
        if (ntile < ntiles) {
            const float4* xr = (const float4*)(x + ((size_t)ntile * 64 + xr_row) * 128 + xr_q * 32);
            #pragma unroll
            for (int e = 0; e < 8; e++) xv[e] = xr[e];
        }

        // ---- quantize: y = y_raw*(sqrt_d/norm); paired-table lookup; write u32 ----
        {
            float mids[15];
            #pragma unroll
            for (int l = 0; l < 15; l++) mids[l] = s_mid[l];
            u32* aW = (u32*)(sm + SM_AH);
            #pragma unroll
            for (int mt = 0; mt < 2; mt++) {
                const int row0 = mrow0 + mt * 16 + g;
                const float sc0 = s_scale[row0];
                const float sc1 = s_scale[row0 + 8];
                #pragma unroll
                for (int nt = 0; nt < 4; nt++) {
                    const int p = (ncol0 >> 1) + nt * 4 + t;
                    const int woff = csw(p >> 2) * 4 + (p & 3);
                    {
                        int i0 = quant_idx(acc[mt][nt][0] * sc0, mids);
                        int i1 = quant_idx(acc[mt][nt][1] * sc0, mids);
                        aW[row0 * 68 + woff] = s_csd2[i0 | (i1 << 4)];
                    }
                    {
                        int i0 = quant_idx(acc[mt][nt][2] * sc1, mids);
                        int i1 = quant_idx(acc[mt][nt][3] * sc1, mids);
                        aW[(row0 + 8) * 68 + woff] = s_csd2[i0 | (i1 << 4)];
                    }
                    acc[mt][nt][0] = 0.f; acc[mt][nt][1] = 0.f;
                    acc[mt][nt][2] = 0.f; acc[mt][nt][3] = 0.f;
                }
            }
        }
        __syncthreads();

        // ---- backward: z = a_hat @ Pi (a_hi * Pi_hi via ldmatrix.trans) ----
        {
            const int cnq = (ncol0 >> 3) + lq;
            const u32 cb0 = (u32)csw(cnq) * 16;
            const u32 cb1 = (u32)csw(cnq + 2) * 16;
            const u32 tbase = sb + SM_PIH + (u32)lrow * RSB;
            #pragma unroll
            for (int ks = 0; ks < 8; ks++) {
                const u32 rb = tbase + (u32)(16 * ks) * RSB;
                const u32 co = (u32)(((2 * ks) ^ (ks & 4)) + lq) * 16;
                u32 th0[4], th1[4], ah0[4], ah1[4];
                LDSM_X4T(th0, rb + cb0);
                LDSM_X4T(th1, rb + cb1);
                LDSM_X4(ah0, aAh0 + co);
                LDSM_X4(ah1, aAh1 + co);
                u32 bh[4][2] = {{th0[0],th0[1]},{th0[2],th0[3]},{th1[0],th1[1]},{th1[2],th1[3]}};
                #pragma unroll
                for (int nt = 0; nt < 4; nt++) {
                    mma16(acc[0][nt], ah0[0], ah0[1], ah0[2], ah0[3], bh[nt][0], bh[nt][1]);
                    mma16(acc[1][nt], ah1[0], ah1[1], ah1[2], ah1[3], bh[nt][0], bh[nt][1]);
                }
            }
        }

        // ---- epilogue: scale by fp16-roundtripped norm, store float2 ----
        #pragma unroll
        for (int mt = 0; mt < 2; mt++) {
            #pragma unroll
            for (int nt = 0; nt < 4; nt++) {
                int row0 = mrow0 + mt * 16 + g;
                int col  = ncol0 + nt * 8 + 2 * t;
                float nh0 = s_nh[row0];
                float nh1 = s_nh[row0 + 8];
                *(float2*)(out + (tok0 + row0) * 128 + col) =
                    make_float2(acc[mt][nt][0] * nh0, acc[mt][nt][1] * nh0);
                *(float2*)(out + (tok0 + row0 + 8) * 128 + col) =
                    make_float2(acc[mt][nt][2] * nh1, acc[mt][nt][3] * nh1);
            }
        }
    }
}

extern "C" void kernel_launch(void* const* d_in, const int* in_sizes, int n_in,
                              void* d_out, int out_size) {
    const float* x   = (const float*)d_in[0];
    const float* Pi  = (const float*)d_in[1];
    const float* cbk = (const float*)d_in[2];
    float* out = (float*)d_out;

    int ntok = in_sizes[0] / 128;
    int ntiles = ntok / 64;

    int dev = 0, nsm = 148;
    cudaGetDevice(&dev);
    cudaDeviceGetAttribute(&nsm, cudaDevAttrMultiProcessorCount, dev);
    int blocks = 2 * nsm;
    if (blocks > ntiles) blocks = ntiles;

    cudaFuncSetAttribute(tq_fused, cudaFuncAttributeMaxDynamicSharedMemorySize, SMEM_BYTES);
    tq_setup<<<8, 256>>>(Pi, cbk);
    tq_fused<<<blocks, 256, SMEM_BYTES>>>(x, out, ntiles);
}